// round 12
// baseline (speedup 1.0000x reference)
#include <cuda_runtime.h>
#include <cuda_fp16.h>
#include <math.h>

#define Bb 64
#define Tt 1024
#define Ii 64
#define Hh 512
#define G3 1536
#define BT (Bb*Tt)
#define NBLK 128
#define BH (Bb*Hh)

// SMEM byte offsets (dynamic smem)
#define OFF_HI   0                       // hi ring: 64 rows x 264 halves = 33792 B
#define OFF_LO   33792                   // lo ring
#define OFF_WF0  67584                   // whh0 frags: 4096 uint2 = 32 KB
#define OFF_WFX  100352                  // wih1 frags
#define OFF_WF1  133120                  // whh1 frags
#define OFF_P1   165888                  // part buf 1: 64x16 f32 = 4 KB
#define OFF_P2   169984                  // part buf 2
#define SMEM_TOTAL_B 174080

// ---------------- scratch (static device allocations only) ----------------
__device__ float g_xg[(size_t)BT * G3];          // layer0 input-side gates
__device__ float g_y[(size_t)BT * Hh];           // layer1 output (FC input)
__device__ __align__(128) __half g_h0hi[2 * BH];
__device__ __align__(128) __half g_h0lo[2 * BH];
__device__ __align__(128) __half g_h1hi[2 * BH];
__device__ __align__(128) __half g_h1lo[2 * BH];
__device__ __align__(128) __half g_y0hi[2 * BH];
__device__ __align__(128) __half g_y0lo[2 * BH];
__device__ float g_wih0T[Ii * G3];
__device__ float g_fcwT[Hh * Ii];
__device__ unsigned int g_arrive;
__device__ unsigned int g_gen;

// ---------------- transpose: in[R][C] -> out[C][R] ----------------
__global__ void transpose_k(const float* __restrict__ in, float* __restrict__ out,
                            int R, int C) {
    __shared__ float tile[32][33];
    int c0 = blockIdx.x * 32, r0 = blockIdx.y * 32;
    int x = threadIdx.x, y = threadIdx.y;
#pragma unroll
    for (int j = 0; j < 32; j += 8)
        tile[y + j][x] = in[(size_t)(r0 + y + j) * C + c0 + x];
    __syncthreads();
#pragma unroll
    for (int j = 0; j < 32; j += 8)
        out[(size_t)(c0 + y + j) * R + r0 + x] = tile[x][y + j];
}

// ---------------- tiled GEMM: out[M][N] = X[M][K] @ Wt[K][N] + bias ----------------
__global__ void gemm_bias(const float* __restrict__ X, const float* __restrict__ Wt,
                          const float* __restrict__ bias, float* __restrict__ out,
                          int M, int K, int N) {
    __shared__ float As[16][64];
    __shared__ float Bs[16][64];
    int tid = threadIdx.x;
    int n0 = blockIdx.x * 64, m0 = blockIdx.y * 64;
    int tx = tid % 16, ty = tid / 16;
    int am = tid / 4, ak = (tid % 4) * 4;
    int bk = tid / 16, bn = (tid % 16) * 4;
    float acc[4][4];
#pragma unroll
    for (int i = 0; i < 4; i++)
#pragma unroll
        for (int j = 0; j < 4; j++) acc[i][j] = 0.f;

    for (int k0 = 0; k0 < K; k0 += 16) {
        float4 av = *(const float4*)&X[(size_t)(m0 + am) * K + k0 + ak];
        As[ak + 0][am] = av.x; As[ak + 1][am] = av.y;
        As[ak + 2][am] = av.z; As[ak + 3][am] = av.w;
        *(float4*)&Bs[bk][bn] = *(const float4*)&Wt[(size_t)(k0 + bk) * N + n0 + bn];
        __syncthreads();
#pragma unroll
        for (int k = 0; k < 16; k++) {
            float4 a = *(const float4*)&As[k][ty * 4];
            float4 b = *(const float4*)&Bs[k][tx * 4];
            acc[0][0] += a.x * b.x; acc[0][1] += a.x * b.y; acc[0][2] += a.x * b.z; acc[0][3] += a.x * b.w;
            acc[1][0] += a.y * b.x; acc[1][1] += a.y * b.y; acc[1][2] += a.y * b.z; acc[1][3] += a.y * b.w;
            acc[2][0] += a.z * b.x; acc[2][1] += a.z * b.y; acc[2][2] += a.z * b.z; acc[2][3] += a.z * b.w;
            acc[3][0] += a.w * b.x; acc[3][1] += a.w * b.y; acc[3][2] += a.w * b.z; acc[3][3] += a.w * b.w;
        }
        __syncthreads();
    }
    float4 bv = *(const float4*)&bias[n0 + tx * 4];
#pragma unroll
    for (int i = 0; i < 4; i++) {
        float4 o;
        o.x = acc[i][0] + bv.x; o.y = acc[i][1] + bv.y;
        o.z = acc[i][2] + bv.z; o.w = acc[i][3] + bv.w;
        *(float4*)&out[(size_t)(m0 + ty * 4 + i) * N + n0 + tx * 4] = o;
    }
}

// ---------------- flat grid barrier (R9 version — best measured) ----------------
__global__ void bar_reset() { g_arrive = 0u; g_gen = 0u; }

__device__ __forceinline__ void grid_barrier(unsigned int target) {
    __syncthreads();
    if (threadIdx.x == 0) {
        __threadfence();
        unsigned int a = atomicAdd(&g_arrive, 1u);
        if (a == NBLK - 1) {
            g_arrive = 0u;
            __threadfence();
            atomicExch(&g_gen, target);
        } else {
            while (*((volatile unsigned int*)&g_gen) < target) {}
            __threadfence();
        }
    }
    __syncthreads();
}

// ---------------- mma / async-copy helpers ----------------
__device__ __forceinline__ void mma16816(float* c, unsigned a0, unsigned a1,
                                         unsigned a2, unsigned a3,
                                         unsigned b0, unsigned b1) {
    asm volatile(
        "mma.sync.aligned.m16n8k16.row.col.f32.f16.f16.f32 "
        "{%0,%1,%2,%3}, {%4,%5,%6,%7}, {%8,%9}, {%0,%1,%2,%3};"
        : "+f"(c[0]), "+f"(c[1]), "+f"(c[2]), "+f"(c[3])
        : "r"(a0), "r"(a1), "r"(a2), "r"(a3), "r"(b0), "r"(b1));
}

__device__ __forceinline__ void ldsm4(unsigned& r0, unsigned& r1, unsigned& r2,
                                      unsigned& r3, unsigned addr) {
    asm volatile("ldmatrix.sync.aligned.m8n8.x4.shared.b16 {%0,%1,%2,%3}, [%4];"
                 : "=r"(r0), "=r"(r1), "=r"(r2), "=r"(r3) : "r"(addr));
}

__device__ __forceinline__ unsigned pack2h(__half a, __half b) {
    return (unsigned)__half_as_ushort(a) | ((unsigned)__half_as_ushort(b) << 16);
}

__device__ __forceinline__ void cpa16(unsigned dst, const void* src) {
    asm volatile("cp.async.cg.shared.global [%0], [%1], 16;" :: "r"(dst), "l"(src));
}
__device__ __forceinline__ void cpa_commit() {
    asm volatile("cp.async.commit_group;" ::: "memory");
}

// stage one k-chunk (64 halves) of both planes into ring slot (c & 3)
__device__ __forceinline__ void stage_chunk(unsigned smem_b, const __half* shi,
                                            const __half* slo, int c, int tid) {
    int slot = c & 3;
#pragma unroll
    for (int u = 0; u < 4; u++) {
        int q = tid + u * 256;            // 0..1023
        int plane = q >> 9;               // 0 hi, 1 lo
        int idx = q & 511;
        int m = idx >> 3, seg = idx & 7;  // 64 rows x 8 segs of 16B
        unsigned dst = smem_b + (plane ? OFF_LO : OFF_HI)
                     + (unsigned)(m * 528 + slot * 128 + seg * 16);
        const __half* src = (plane ? slo : shi) + m * 512 + c * 64 + seg * 8;
        cpa16(dst, src);
    }
}

__device__ __forceinline__ void prologue3(unsigned smem_b, const __half* shi,
                                          const __half* slo, int tid) {
    stage_chunk(smem_b, shi, slo, 0, tid); cpa_commit();
    stage_chunk(smem_b, shi, slo, 1, tid); cpa_commit();
    stage_chunk(smem_b, shi, slo, 2, tid); cpa_commit();
}

// one chunk-pipelined split-fp16 mma phase over K=512; writes 64x16 part buffer.
// Requires: prologue3 already issued for (shi, slo).
__device__ __forceinline__ void mma_phase(unsigned smem_b, unsigned bbase,
                                          unsigned a_hi, unsigned a_lo,
                                          const __half* shi, const __half* slo,
                                          int tid, int lane, int mi, int ni,
                                          float* partbuf) {
    float chh[4] = {0.f, 0.f, 0.f, 0.f};
    float chl[4] = {0.f, 0.f, 0.f, 0.f};
    float clh[4] = {0.f, 0.f, 0.f, 0.f};
#pragma unroll
    for (int c = 0; c < 8; c++) {
        if (c < 6)      asm volatile("cp.async.wait_group 2;" ::: "memory");
        else if (c == 6) asm volatile("cp.async.wait_group 1;" ::: "memory");
        else             asm volatile("cp.async.wait_group 0;" ::: "memory");
        __syncthreads();
        if (c < 5) { stage_chunk(smem_b, shi, slo, c + 3, tid); cpa_commit(); }
        int slot = c & 3;
#pragma unroll
        for (int sl = 0; sl < 4; sl++) {
            int s = c * 4 + sl;
            unsigned Aoff = (unsigned)(slot * 128 + sl * 32);
            unsigned Ah0, Ah1, Ah2, Ah3, Al0, Al1, Al2, Al3;
            ldsm4(Ah0, Ah1, Ah2, Ah3, a_hi + Aoff);
            ldsm4(Al0, Al1, Al2, Al3, a_lo + Aoff);
            unsigned bh0, bh1, bl0, bl1;
            asm volatile("ld.shared.v2.u32 {%0,%1}, [%2];"
                         : "=r"(bh0), "=r"(bh1) : "r"(bbase + s * 512));
            asm volatile("ld.shared.v2.u32 {%0,%1}, [%2];"
                         : "=r"(bl0), "=r"(bl1) : "r"(bbase + s * 512 + 256));
            mma16816(chh, Ah0, Ah1, Ah2, Ah3, bh0, bh1);
            mma16816(chl, Ah0, Ah1, Ah2, Ah3, bl0, bl1);
            mma16816(clh, Al0, Al1, Al2, Al3, bh0, bh1);
        }
    }
    float d0 = chh[0] + chl[0] + clh[0];
    float d1 = chh[1] + chl[1] + clh[1];
    float d2 = chh[2] + chl[2] + clh[2];
    float d3 = chh[3] + chl[3] + clh[3];
    int r = lane >> 2, tc = (lane & 3) * 2;
    int b = mi * 16 + r;
    int c0 = ni * 8 + tc;
    if (c0 < 12)     { partbuf[b * 16 + c0]     = d0; partbuf[(b + 8) * 16 + c0]     = d2; }
    if (c0 + 1 < 12) { partbuf[b * 16 + c0 + 1] = d1; partbuf[(b + 8) * 16 + c0 + 1] = d3; }
}

// one-time fragment prep: W rows (K-major [3H][512]) -> mma B-frag order in smem
__device__ __forceinline__ void prep_frags(uint2* wfp, const float* wsrc, int j0, int tid) {
    for (int q = tid; q < 4096; q += 256) {
        int l = q & 31, ps = (q >> 5) & 1, s = (q >> 6) & 31, nn = q >> 11;
        int c = nn * 8 + (l >> 2), t = l & 3;
        float e0 = 0.f, e1 = 0.f, e2 = 0.f, e3 = 0.f;
        if (c < 12) {
            int g = c >> 2, jj = c & 3;
            const float* wr = wsrc + (size_t)(g * Hh + j0 + jj) * Hh;
            int k = s * 16 + t * 2;
            e0 = wr[k]; e1 = wr[k + 1]; e2 = wr[k + 8]; e3 = wr[k + 9];
        }
        __half h0 = __float2half_rn(e0), h1 = __float2half_rn(e1);
        __half h2v = __float2half_rn(e2), h3 = __float2half_rn(e3);
        if (ps) {
            h0 = __float2half_rn(e0 - __half2float(h0));
            h1 = __float2half_rn(e1 - __half2float(h1));
            h2v = __float2half_rn(e2 - __half2float(h2v));
            h3 = __float2half_rn(e3 - __half2float(h3));
        }
        uint2 v; v.x = pack2h(h0, h1); v.y = pack2h(h2v, h3);
        wfp[q] = v;
    }
}

// ---------------- fused 2-layer persistent GRU ----------------
// 128 blocks x 256 threads. Block bid owns h-cols j0..j0+3 of BOTH layers.
// Round r: layer0 computes step t0=r (if <Tt); layer1 computes step t1=r-1 (if >=0).
__global__ void __launch_bounds__(256, 1)
gru_fused(const float* __restrict__ xg,
          const float* __restrict__ whh0, const float* __restrict__ bhh0,
          const float* __restrict__ wih1, const float* __restrict__ whh1,
          const float* __restrict__ bih1, const float* __restrict__ bhh1,
          __half* __restrict__ h0hi, __half* __restrict__ h0lo,
          __half* __restrict__ h1hi, __half* __restrict__ h1lo,
          __half* __restrict__ y0hi, __half* __restrict__ y0lo,
          float* __restrict__ y) {
    extern __shared__ unsigned char smraw[];
    float* part1 = (float*)(smraw + OFF_P1);
    float* part2 = (float*)(smraw + OFF_P2);
    const unsigned smem_b = (unsigned)__cvta_generic_to_shared(smraw);

    const int tid = threadIdx.x, bid = blockIdx.x;
    const int j0 = bid * 4;
    const int lane = tid & 31, wid = tid >> 5;
    const int mi = wid >> 1, ni = wid & 1;

    // one-time fragment prep (3 weight matrices)
    prep_frags((uint2*)(smraw + OFF_WF0), whh0, j0, tid);
    prep_frags((uint2*)(smraw + OFF_WFX), wih1, j0, tid);
    prep_frags((uint2*)(smraw + OFF_WF1), whh1, j0, tid);

    // zero slot-0 h planes (both layers); exact h in registers
    {
        int i = bid * 256 + tid;   // exactly BH chip-wide
        __half z = __float2half_rn(0.f);
        h0hi[i] = z; h0lo[i] = z; h1hi[i] = z; h1lo[i] = z;
    }
    float h0own = 0.f, h1own = 0.f;

    // per-thread gate constants
    const int ub = tid >> 2, uj = tid & 3;
    const float b0r = bhh0[j0 + uj];
    const float b0z = bhh0[Hh + j0 + uj];
    const float b0n = bhh0[2 * Hh + j0 + uj];
    const float b1r = bih1[j0 + uj] + bhh1[j0 + uj];
    const float b1z = bih1[Hh + j0 + uj] + bhh1[Hh + j0 + uj];
    const float b1xn = bih1[2 * Hh + j0 + uj];
    const float b1hn = bhh1[2 * Hh + j0 + uj];
    const float* xp = xg + (size_t)ub * Tt * G3 + j0 + uj;
    float* yp = y + (size_t)ub * Tt * Hh + j0 + uj;

    // ldmatrix A addresses (ring layout: rows of 264 halves per plane)
    const unsigned aoff = (unsigned)((mi * 16 + (lane & 15)) * 528 + (lane >> 4) * 16);
    const unsigned a_hi = smem_b + OFF_HI + aoff;
    const unsigned a_lo = smem_b + OFF_LO + aoff;
    const unsigned bb0 = smem_b + OFF_WF0 + (unsigned)(ni * 16384 + lane * 8);
    const unsigned bbX = smem_b + OFF_WFX + (unsigned)(ni * 16384 + lane * 8);
    const unsigned bb1 = smem_b + OFF_WF1 + (unsigned)(ni * 16384 + lane * 8);

    unsigned int bar = 0;
    grid_barrier(++bar);

    for (int r = 0; r <= Tt; r++) {
        const int t0 = r, t1 = r - 1;
        const bool do0 = (t0 < Tt), do1 = (t1 >= 0);

        float xr = 0.f, xz = 0.f, xn = 0.f;
        if (do0) {
            // prefetch layer0 x-side gates (DRAM; consumed after mma)
            xr = xp[(size_t)t0 * G3];
            xz = xp[(size_t)t0 * G3 + Hh];
            xn = xp[(size_t)t0 * G3 + 2 * Hh];
            // ---- phase A: hg0 = whh0 @ h0 ----
            const __half* shi = h0hi + (t0 & 1) * BH;
            const __half* slo = h0lo + (t0 & 1) * BH;
            prologue3(smem_b, shi, slo, tid);
            mma_phase(smem_b, bb0, a_hi, a_lo, shi, slo, tid, lane, mi, ni, part1);
        }
        // hoist phase-X staging before gates0 (reads last round's y0 — independent)
        const __half* sxhi = y0hi + (t1 & 1) * BH;
        const __half* sxlo = y0lo + (t1 & 1) * BH;
        if (do1) prologue3(smem_b, sxhi, sxlo, tid);
        __syncthreads();   // part1 visible for gates0

        if (do0) {
            // ---- layer0 gate update ----
            float hr = b0r + part1[ub * 16 + uj];
            float hz = b0z + part1[ub * 16 + 4 + uj];
            float hn_ = b0n + part1[ub * 16 + 8 + uj];
            float rr = 1.f / (1.f + expf(-(xr + hr)));
            float zz = 1.f / (1.f + expf(-(xz + hz)));
            float nn = tanhf(xn + rr * hn_);
            float v = (1.f - zz) * nn + zz * h0own;
            h0own = v;
            __half vh = __float2half_rn(v);
            __half vl = __float2half_rn(v - __half2float(vh));
            int widx = ((t0 + 1) & 1) * BH + ub * Hh + j0 + uj;
            h0hi[widx] = vh; h0lo[widx] = vl;
            int yidx = (t0 & 1) * BH + ub * Hh + j0 + uj;
            y0hi[yidx] = vh; y0lo[yidx] = vl;
        }

        if (do1) {
            // ---- phase X: xg1 = wih1 @ y0[t1] ----
            mma_phase(smem_b, bbX, a_hi, a_lo, sxhi, sxlo, tid, lane, mi, ni, part1);
            // ---- phase H: hg1 = whh1 @ h1[t1] ----
            const __half* shhi = h1hi + (t1 & 1) * BH;
            const __half* shlo = h1lo + (t1 & 1) * BH;
            prologue3(smem_b, shhi, shlo, tid);
            mma_phase(smem_b, bb1, a_hi, a_lo, shhi, shlo, tid, lane, mi, ni, part2);
            __syncthreads();   // part1 (X) + part2 (H) visible

            // ---- layer1 gate update ----
            float sr = b1r + part1[ub * 16 + uj]      + part2[ub * 16 + uj];
            float sz = b1z + part1[ub * 16 + 4 + uj]  + part2[ub * 16 + 4 + uj];
            float xn1 = b1xn + part1[ub * 16 + 8 + uj];
            float hn1 = b1hn + part2[ub * 16 + 8 + uj];
            float rr = 1.f / (1.f + expf(-sr));
            float zz = 1.f / (1.f + expf(-sz));
            float nn = tanhf(xn1 + rr * hn1);
            float v = (1.f - zz) * nn + zz * h1own;
            h1own = v;
            __half vh = __float2half_rn(v);
            __half vl = __float2half_rn(v - __half2float(vh));
            int widx = ((t1 + 1) & 1) * BH + ub * Hh + j0 + uj;
            h1hi[widx] = vh; h1lo[widx] = vl;
            yp[(size_t)t1 * Hh] = v;
        }
        grid_barrier(++bar);
    }
}

// ---------------- launch ----------------
extern "C" void kernel_launch(void* const* d_in, const int* in_sizes, int n_in,
                              void* d_out, int out_size) {
    const float* x     = (const float*)d_in[0];
    const float* w_ih0 = (const float*)d_in[1];
    const float* w_hh0 = (const float*)d_in[2];
    const float* b_ih0 = (const float*)d_in[3];
    const float* b_hh0 = (const float*)d_in[4];
    const float* w_ih1 = (const float*)d_in[5];
    const float* w_hh1 = (const float*)d_in[6];
    const float* b_ih1 = (const float*)d_in[7];
    const float* b_hh1 = (const float*)d_in[8];
    const float* fc_w  = (const float*)d_in[9];
    const float* fc_b  = (const float*)d_in[10];
    float* out = (float*)d_out;

    float *xg, *y, *wih0T, *fcwT;
    __half *h0hi, *h0lo, *h1hi, *h1lo, *y0hi, *y0lo;
    cudaGetSymbolAddress((void**)&xg,    g_xg);
    cudaGetSymbolAddress((void**)&y,     g_y);
    cudaGetSymbolAddress((void**)&h0hi,  g_h0hi);
    cudaGetSymbolAddress((void**)&h0lo,  g_h0lo);
    cudaGetSymbolAddress((void**)&h1hi,  g_h1hi);
    cudaGetSymbolAddress((void**)&h1lo,  g_h1lo);
    cudaGetSymbolAddress((void**)&y0hi,  g_y0hi);
    cudaGetSymbolAddress((void**)&y0lo,  g_y0lo);
    cudaGetSymbolAddress((void**)&wih0T, g_wih0T);
    cudaGetSymbolAddress((void**)&fcwT,  g_fcwT);

    cudaFuncSetAttribute(gru_fused,
                         cudaFuncAttributeMaxDynamicSharedMemorySize, SMEM_TOTAL_B);

    dim3 tb(32, 8);
    transpose_k<<<dim3(Ii / 32, G3 / 32), tb>>>(w_ih0, wih0T, G3, Ii);
    transpose_k<<<dim3(Hh / 32, Ii / 32), tb>>>(fc_w,  fcwT,  Ii, Hh);

    // layer0 input-side gates (K=64, cheap)
    gemm_bias<<<dim3(G3 / 64, BT / 64), 256>>>(x, wih0T, b_ih0, xg, BT, Ii, G3);

    // fused 2-layer recurrence
    bar_reset<<<1, 1>>>();
    gru_fused<<<NBLK, 256, SMEM_TOTAL_B>>>(xg, w_hh0, b_hh0, w_ih1, w_hh1,
                                           b_ih1, b_hh1, h0hi, h0lo, h1hi, h1lo,
                                           y0hi, y0lo, y);

    // final FC
    gemm_bias<<<dim3(Ii / 64, BT / 64), 256>>>(y, fcwT, fc_b, out, BT, Hh, Ii);
}

// round 14
// speedup vs baseline: 1.3857x; 1.3857x over previous
#include <cuda_runtime.h>
#include <cuda_fp16.h>
#include <math.h>

#define Bb 64
#define Tt 1024
#define Ii 64
#define Hh 512
#define G3 1536
#define BT (Bb*Tt)
#define NBLK 128
#define BH (Bb*Hh)

// SMEM byte offsets (dynamic smem)
#define OFF_HI   0                       // h plane ring: 64 rows x 520 halves = 66560 B
#define OFF_WF   66560                   // w fragments: 2048 uint2 = 16 KB
#define OFF_PART 82944                   // 64x12 f32 = 3 KB
#define OFF_OWN  86016                   // 64x4 f32 exact h
#define SMEM_TOTAL_B 87040

// ---------------- scratch (static device allocations only) ----------------
__device__ float g_xg[(size_t)BT * G3];
__device__ float g_y[(size_t)BT * Hh];
__device__ __align__(128) __half g_hhi[2 * BH];   // fp16 hidden, ping-pong [b][hidden]
__device__ float g_wih0T[Ii * G3];
__device__ float g_wih1T[Hh * G3];
__device__ float g_fcwT[Hh * Ii];
__device__ unsigned int g_arrive;
__device__ unsigned int g_gen;

// ---------------- transpose: in[R][C] -> out[C][R] ----------------
__global__ void transpose_k(const float* __restrict__ in, float* __restrict__ out,
                            int R, int C) {
    __shared__ float tile[32][33];
    int c0 = blockIdx.x * 32, r0 = blockIdx.y * 32;
    int x = threadIdx.x, y = threadIdx.y;
#pragma unroll
    for (int j = 0; j < 32; j += 8)
        tile[y + j][x] = in[(size_t)(r0 + y + j) * C + c0 + x];
    __syncthreads();
#pragma unroll
    for (int j = 0; j < 32; j += 8)
        out[(size_t)(c0 + y + j) * R + r0 + x] = tile[x][y + j];
}

// ---------------- tiled GEMM: out[M][N] = X[M][K] @ Wt[K][N] + bias ----------------
__global__ void gemm_bias(const float* __restrict__ X, const float* __restrict__ Wt,
                          const float* __restrict__ bias, float* __restrict__ out,
                          int M, int K, int N) {
    __shared__ float As[16][64];
    __shared__ float Bs[16][64];
    int tid = threadIdx.x;
    int n0 = blockIdx.x * 64, m0 = blockIdx.y * 64;
    int tx = tid % 16, ty = tid / 16;
    int am = tid / 4, ak = (tid % 4) * 4;
    int bk = tid / 16, bn = (tid % 16) * 4;
    float acc[4][4];
#pragma unroll
    for (int i = 0; i < 4; i++)
#pragma unroll
        for (int j = 0; j < 4; j++) acc[i][j] = 0.f;

    for (int k0 = 0; k0 < K; k0 += 16) {
        float4 av = *(const float4*)&X[(size_t)(m0 + am) * K + k0 + ak];
        As[ak + 0][am] = av.x; As[ak + 1][am] = av.y;
        As[ak + 2][am] = av.z; As[ak + 3][am] = av.w;
        *(float4*)&Bs[bk][bn] = *(const float4*)&Wt[(size_t)(k0 + bk) * N + n0 + bn];
        __syncthreads();
#pragma unroll
        for (int k = 0; k < 16; k++) {
            float4 a = *(const float4*)&As[k][ty * 4];
            float4 b = *(const float4*)&Bs[k][tx * 4];
            acc[0][0] += a.x * b.x; acc[0][1] += a.x * b.y; acc[0][2] += a.x * b.z; acc[0][3] += a.x * b.w;
            acc[1][0] += a.y * b.x; acc[1][1] += a.y * b.y; acc[1][2] += a.y * b.z; acc[1][3] += a.y * b.w;
            acc[2][0] += a.z * b.x; acc[2][1] += a.z * b.y; acc[2][2] += a.z * b.z; acc[2][3] += a.z * b.w;
            acc[3][0] += a.w * b.x; acc[3][1] += a.w * b.y; acc[3][2] += a.w * b.z; acc[3][3] += a.w * b.w;
        }
        __syncthreads();
    }
    float4 bv = *(const float4*)&bias[n0 + tx * 4];
#pragma unroll
    for (int i = 0; i < 4; i++) {
        float4 o;
        o.x = acc[i][0] + bv.x; o.y = acc[i][1] + bv.y;
        o.z = acc[i][2] + bv.z; o.w = acc[i][3] + bv.w;
        *(float4*)&out[(size_t)(m0 + ty * 4 + i) * N + n0 + tx * 4] = o;
    }
}

// ---------------- flat grid barrier (best measured) ----------------
__global__ void bar_reset() { g_arrive = 0u; g_gen = 0u; }

__device__ __forceinline__ void grid_barrier(unsigned int target) {
    __syncthreads();
    if (threadIdx.x == 0) {
        __threadfence();
        unsigned int a = atomicAdd(&g_arrive, 1u);
        if (a == NBLK - 1) {
            g_arrive = 0u;
            __threadfence();
            atomicExch(&g_gen, target);
        } else {
            while (*((volatile unsigned int*)&g_gen) < target) {}
            __threadfence();
        }
    }
    __syncthreads();
}

// ---------------- mma / async-copy helpers ----------------
__device__ __forceinline__ void mma16816(float* c, unsigned a0, unsigned a1,
                                         unsigned a2, unsigned a3,
                                         unsigned b0, unsigned b1) {
    asm volatile(
        "mma.sync.aligned.m16n8k16.row.col.f32.f16.f16.f32 "
        "{%0,%1,%2,%3}, {%4,%5,%6,%7}, {%8,%9}, {%0,%1,%2,%3};"
        : "+f"(c[0]), "+f"(c[1]), "+f"(c[2]), "+f"(c[3])
        : "r"(a0), "r"(a1), "r"(a2), "r"(a3), "r"(b0), "r"(b1));
}

__device__ __forceinline__ void ldsm4(unsigned& r0, unsigned& r1, unsigned& r2,
                                      unsigned& r3, unsigned addr) {
    asm volatile("ldmatrix.sync.aligned.m8n8.x4.shared.b16 {%0,%1,%2,%3}, [%4];"
                 : "=r"(r0), "=r"(r1), "=r"(r2), "=r"(r3) : "r"(addr));
}

__device__ __forceinline__ unsigned pack2h(__half a, __half b) {
    return (unsigned)__half_as_ushort(a) | ((unsigned)__half_as_ushort(b) << 16);
}

__device__ __forceinline__ void cpa16(unsigned dst, const void* src) {
    asm volatile("cp.async.cg.shared.global [%0], [%1], 16;" :: "r"(dst), "l"(src));
}
__device__ __forceinline__ void cpa_commit() {
    asm volatile("cp.async.commit_group;" ::: "memory");
}

__device__ __forceinline__ float fsig(float x) {
    return 1.f / (1.f + __expf(-x));
}
__device__ __forceinline__ float ftanh(float x) {
    return 2.f / (1.f + __expf(-2.f * x)) - 1.f;
}

// stage one k-chunk (128 halves of K) of the h plane: 64 rows x 256 B
__device__ __forceinline__ void stage_chunk(unsigned smem_b, const __half* shi,
                                            int c, int tid) {
#pragma unroll
    for (int u = 0; u < 4; u++) {
        int q = tid + u * 256;            // 0..1023
        int m = q >> 4, seg = q & 15;     // 64 rows x 16 segs of 16B
        cpa16(smem_b + OFF_HI + (unsigned)(m * 1040 + c * 256 + seg * 16),
              shi + m * 512 + c * 128 + seg * 8);
    }
}

// ---------------- persistent single-fp16 tensor-core GRU layer ----------------
// 128 blocks x 256 threads (8 warps). Block bid owns h-cols j0..j0+3.
// warp wid: mi = wid>>1 (rows mi*16..+16), ni = wid&1 (cols ni*8..+8 of 12).
__global__ void __launch_bounds__(256, 1)
gru_layer_mma(const float* __restrict__ xg, const float* __restrict__ whh,
              const float* __restrict__ bhh, __half* __restrict__ hhi,
              float* __restrict__ y) {
    extern __shared__ unsigned char smraw[];
    float* part = (float*)(smraw + OFF_PART);
    float* own  = (float*)(smraw + OFF_OWN);
    uint2* wf   = (uint2*)(smraw + OFF_WF);
    const unsigned smem_b = (unsigned)__cvta_generic_to_shared(smraw);

    const int tid = threadIdx.x, bid = blockIdx.x;
    const int j0 = bid * 4;
    const int lane = tid & 31, wid = tid >> 5;
    const int mi = wid >> 1, ni = wid & 1;

    // ---- one-time: W_hh fragments (fp16, mma B-frag order, single plane) ----
    for (int q = tid; q < 2048; q += 256) {
        int l = q & 31, s = (q >> 5) & 31, nn = q >> 10;
        int c = nn * 8 + (l >> 2), t = l & 3;
        float e0 = 0.f, e1 = 0.f, e2 = 0.f, e3 = 0.f;
        if (c < 12) {
            int g = c >> 2, jj = c & 3;
            const float* wr = whh + (size_t)(g * Hh + j0 + jj) * Hh;
            int k = s * 16 + t * 2;
            e0 = wr[k]; e1 = wr[k + 1]; e2 = wr[k + 8]; e3 = wr[k + 9];
        }
        uint2 v;
        v.x = pack2h(__float2half_rn(e0), __float2half_rn(e1));
        v.y = pack2h(__float2half_rn(e2), __float2half_rn(e3));
        wf[q] = v;
    }

    // zero h plane slot 0 + own exact-h
    {
        int i = bid * 256 + tid;   // exactly BH chip-wide
        hhi[i] = __float2half_rn(0.f);
    }
    own[tid] = 0.f;

    // hoisted per-thread constants for the update phase
    const int ub = tid >> 2, uj = tid & 3;
    const float bhr = bhh[j0 + uj];
    const float bhz = bhh[Hh + j0 + uj];
    const float bhn = bhh[2 * Hh + j0 + uj];
    const float* xp = xg + (size_t)ub * Tt * G3 + j0 + uj;
    float* yp = y + (size_t)ub * Tt * Hh + j0 + uj;

    // ldmatrix A address; B frag address
    const unsigned aoff = (unsigned)((mi * 16 + (lane & 15)) * 1040 + (lane >> 4) * 16);
    const unsigned a_hi = smem_b + OFF_HI + aoff;
    const unsigned bbase = smem_b + OFF_WF + (unsigned)(ni * 8192 + lane * 8);

    unsigned int bar = 0;
    grid_barrier(++bar);

    for (int t = 0; t < Tt; t++) {
        const __half* shi = hhi + (t & 1) * BH;
        __half* nhi = hhi + ((t + 1) & 1) * BH;

        // prefetch xg (DRAM) for the gate phase
        float xr = xp[(size_t)t * G3];
        float xz = xp[(size_t)t * G3 + Hh];
        float xn = xp[(size_t)t * G3 + 2 * Hh];

        // ---- pipelined stage + mma over 4 k-chunks (128 halves each) ----
        float acc0[4] = {0.f, 0.f, 0.f, 0.f};
        float acc1[4] = {0.f, 0.f, 0.f, 0.f};

        stage_chunk(smem_b, shi, 0, tid);
        cpa_commit();

#pragma unroll
        for (int c = 0; c < 4; c++) {
            if (c < 3) {
                stage_chunk(smem_b, shi, c + 1, tid);
                cpa_commit();
                asm volatile("cp.async.wait_group 1;" ::: "memory");
            } else {
                asm volatile("cp.async.wait_group 0;" ::: "memory");
            }
            __syncthreads();
#pragma unroll
            for (int sl = 0; sl < 8; sl++) {
                int s = c * 8 + sl;
                unsigned A0, A1, A2, A3;
                ldsm4(A0, A1, A2, A3, a_hi + s * 32);
                unsigned b0, b1;
                asm volatile("ld.shared.v2.u32 {%0,%1}, [%2];"
                             : "=r"(b0), "=r"(b1) : "r"(bbase + s * 256));
                mma16816((sl & 1) ? acc1 : acc0, A0, A1, A2, A3, b0, b1);
            }
        }
        {
            float d0 = acc0[0] + acc1[0];
            float d1 = acc0[1] + acc1[1];
            float d2 = acc0[2] + acc1[2];
            float d3 = acc0[3] + acc1[3];
            int r = lane >> 2, tc = (lane & 3) * 2;
            int b = mi * 16 + r;
            int c0 = ni * 8 + tc;
            if (c0 < 12)     { part[b * 12 + c0]     = d0; part[(b + 8) * 12 + c0]     = d2; }
            if (c0 + 1 < 12) { part[b * 12 + c0 + 1] = d1; part[(b + 8) * 12 + c0 + 1] = d3; }
        }
        __syncthreads();

        // ---- gate update (all 256 threads: (b, j)) ----
        {
            float hr = bhr + part[ub * 12 + uj];
            float hz = bhz + part[ub * 12 + 4 + uj];
            float hn_ = bhn + part[ub * 12 + 8 + uj];
            float r = fsig(xr + hr);
            float z = fsig(xz + hz);
            float n = ftanh(xn + r * hn_);
            float hp = own[ub * 4 + uj];
            float v = (1.f - z) * n + z * hp;
            own[ub * 4 + uj] = v;
            nhi[ub * Hh + j0 + uj] = __float2half_rn(v);
            yp[(size_t)t * Hh] = v;
        }
        grid_barrier(++bar);
    }
}

// ---------------- launch ----------------
extern "C" void kernel_launch(void* const* d_in, const int* in_sizes, int n_in,
                              void* d_out, int out_size) {
    const float* x     = (const float*)d_in[0];
    const float* w_ih0 = (const float*)d_in[1];
    const float* w_hh0 = (const float*)d_in[2];
    const float* b_ih0 = (const float*)d_in[3];
    const float* b_hh0 = (const float*)d_in[4];
    const float* w_ih1 = (const float*)d_in[5];
    const float* w_hh1 = (const float*)d_in[6];
    const float* b_ih1 = (const float*)d_in[7];
    const float* b_hh1 = (const float*)d_in[8];
    const float* fc_w  = (const float*)d_in[9];
    const float* fc_b  = (const float*)d_in[10];
    float* out = (float*)d_out;

    float *xg, *y, *wih0T, *wih1T, *fcwT;
    __half* hhi;
    cudaGetSymbolAddress((void**)&xg,    g_xg);
    cudaGetSymbolAddress((void**)&y,     g_y);
    cudaGetSymbolAddress((void**)&hhi,   g_hhi);
    cudaGetSymbolAddress((void**)&wih0T, g_wih0T);
    cudaGetSymbolAddress((void**)&wih1T, g_wih1T);
    cudaGetSymbolAddress((void**)&fcwT,  g_fcwT);

    cudaFuncSetAttribute(gru_layer_mma,
                         cudaFuncAttributeMaxDynamicSharedMemorySize, SMEM_TOTAL_B);

    dim3 tb(32, 8);
    transpose_k<<<dim3(Ii / 32, G3 / 32), tb>>>(w_ih0, wih0T, G3, Ii);
    transpose_k<<<dim3(Hh / 32, G3 / 32), tb>>>(w_ih1, wih1T, G3, Hh);
    transpose_k<<<dim3(Hh / 32, Ii / 32), tb>>>(fc_w,  fcwT,  Ii, Hh);

    // -------- layer 0 --------
    gemm_bias<<<dim3(G3 / 64, BT / 64), 256>>>(x, wih0T, b_ih0, xg, BT, Ii, G3);
    bar_reset<<<1, 1>>>();
    gru_layer_mma<<<NBLK, 256, SMEM_TOTAL_B>>>(xg, w_hh0, b_hh0, hhi, y);

    // -------- layer 1 --------
    gemm_bias<<<dim3(G3 / 64, BT / 64), 256>>>(y, wih1T, b_ih1, xg, BT, Hh, G3);
    bar_reset<<<1, 1>>>();
    gru_layer_mma<<<NBLK, 256, SMEM_TOTAL_B>>>(xg, w_hh1, b_hh1, hhi, y);

    // -------- final FC --------
    gemm_bias<<<dim3(Ii / 64, BT / 64), 256>>>(y, fcwT, fc_b, out, BT, Hh, Ii);
}